// round 13
// baseline (speedup 1.0000x reference)
#include <cuda_runtime.h>
#include <cuda_fp16.h>
#include <math.h>
#include <float.h>
#include <stdint.h>

#define N_NODES 50000
#define N_EDGES 1600000
#define E_TOT   1650000      // edges + self loops
#define IN_CH   128
#define HC      128          // HEADS * OUT_CH
#define HEADS   4
#define NHC     (N_NODES * HC)   // 6,400,000
#define NEG_SLOPE 0.2f

#define SB 1024
#define NB ((N_NODES + SB - 1) / SB)   // 49 scan blocks

// GEMM tile config
#define GP 136                       // smem pitch in halves (conflict-free for ldmatrix)
#define GEMM_SMEM (4 * 128 * GP * 2) // sAh, sAl, sWh, sWl

// ---------------- device scratch (static: no allocations allowed) ----------------
__device__ __align__(16) __half g_hh[(size_t)NHC];   // projected features fp16 [N,128]
__device__ __align__(16) float g_asrc[N_NODES * HEADS];
__device__ __align__(16) float g_adst[N_NODES * HEADS];
__device__ int   g_cnt[N_NODES];                     // zero-init; self-reset by k_writeoff
__device__ int   g_cur[N_NODES];
__device__ int   g_rowstart[N_NODES + 1];
__device__ int   g_bsum[NB];
__device__ int   g_boff[NB];
__device__ __align__(16) int2   g_sed[E_TOT];        // {src, edge_id} grouped by dst
__device__ __align__(16) float4 g_ex[E_TOT];         // exp(leaky(logit)) per head, CSR order

// ---------------- tensor-core helpers ----------------
#define LDSM4(r0, r1, r2, r3, addr) \
    asm volatile("ldmatrix.sync.aligned.m8n8.x4.shared.b16 {%0,%1,%2,%3}, [%4];" \
                 : "=r"(r0), "=r"(r1), "=r"(r2), "=r"(r3) : "r"(addr))
#define LDSM4T(r0, r1, r2, r3, addr) \
    asm volatile("ldmatrix.sync.aligned.m8n8.x4.trans.shared.b16 {%0,%1,%2,%3}, [%4];" \
                 : "=r"(r0), "=r"(r1), "=r"(r2), "=r"(r3) : "r"(addr))
#define MMA16816(d, a, b0, b1) \
    asm volatile("mma.sync.aligned.m16n8k16.row.col.f32.f16.f16.f32 " \
                 "{%0,%1,%2,%3},{%4,%5,%6,%7},{%8,%9},{%0,%1,%2,%3};" \
                 : "+f"(d[0]), "+f"(d[1]), "+f"(d[2]), "+f"(d[3]) \
                 : "r"(a[0]), "r"(a[1]), "r"(a[2]), "r"(a[3]), "r"(b0), "r"(b1))

__device__ __forceinline__ uint32_t pack_hi(float a, float b) {
    __half2 h = __floats2half2_rn(a, b);
    return *(uint32_t*)&h;
}

// ---------------- K1: h = x @ W via split-fp16 HMMA + fused att dots ----------------
__global__ __launch_bounds__(256, 1) void k_gemm(const float* __restrict__ x,
                                                 const float* __restrict__ W,
                                                 const float* __restrict__ att_src,
                                                 const float* __restrict__ att_dst) {
    extern __shared__ __half sm[];
    __half* sAh = sm;
    __half* sAl = sm + 128 * GP;
    __half* sWh = sm + 2 * 128 * GP;
    __half* sWl = sm + 3 * 128 * GP;

    const int tid = threadIdx.x;
    const int m0  = blockIdx.x * 128;

    const float4* W4 = (const float4*)W;
    for (int i = tid; i < 128 * 32; i += 256) {
        int r = i >> 5, c4 = i & 31;
        float4 wv = W4[i];
        __half h0 = __float2half_rn(wv.x), h1 = __float2half_rn(wv.y);
        __half h2 = __float2half_rn(wv.z), h3 = __float2half_rn(wv.w);
        uint32_t hi01 = pack_hi(wv.x, wv.y), hi23 = pack_hi(wv.z, wv.w);
        uint32_t lo01 = pack_hi(wv.x - __half2float(h0), wv.y - __half2float(h1));
        uint32_t lo23 = pack_hi(wv.z - __half2float(h2), wv.w - __half2float(h3));
        uint32_t off = r * GP + c4 * 4;
        *(uint2*)(sWh + off) = make_uint2(hi01, hi23);
        *(uint2*)(sWl + off) = make_uint2(lo01, lo23);
    }
    const float4* x4 = (const float4*)x;
    for (int i = tid; i < 128 * 32; i += 256) {
        int r = i >> 5, c4 = i & 31;
        int gr = m0 + r;
        float4 v = make_float4(0.f, 0.f, 0.f, 0.f);
        if (gr < N_NODES) v = x4[(size_t)gr * 32 + c4];
        __half h0 = __float2half_rn(v.x), h1 = __float2half_rn(v.y);
        __half h2 = __float2half_rn(v.z), h3 = __float2half_rn(v.w);
        uint32_t hi01 = pack_hi(v.x, v.y), hi23 = pack_hi(v.z, v.w);
        uint32_t lo01 = pack_hi(v.x - __half2float(h0), v.y - __half2float(h1));
        uint32_t lo23 = pack_hi(v.z - __half2float(h2), v.w - __half2float(h3));
        uint32_t off = r * GP + c4 * 4;
        *(uint2*)(sAh + off) = make_uint2(hi01, hi23);
        *(uint2*)(sAl + off) = make_uint2(lo01, lo23);
    }
    __syncthreads();

    const int w = tid >> 5, l = tid & 31;

    float acc[16][4];
#pragma unroll
    for (int t = 0; t < 16; t++)
#pragma unroll
        for (int j = 0; j < 4; j++) acc[t][j] = 0.f;

    int a_m = (w << 4) + (((l >> 3) & 1) << 3) + (l & 7);
    int a_k = ((l >> 4) << 3);
    uint32_t aAh = (uint32_t)__cvta_generic_to_shared(sAh) + (a_m * GP + a_k) * 2;
    uint32_t aAl = (uint32_t)__cvta_generic_to_shared(sAl) + (a_m * GP + a_k) * 2;
    int b_k = (((l >> 3) & 1) << 3) + (l & 7);
    int b_n = ((l >> 4) << 3);
    uint32_t aWh = (uint32_t)__cvta_generic_to_shared(sWh) + (b_k * GP + b_n) * 2;
    uint32_t aWl = (uint32_t)__cvta_generic_to_shared(sWl) + (b_k * GP + b_n) * 2;

#pragma unroll
    for (int ks = 0; ks < 8; ks++) {
        uint32_t Ah[4], Al[4];
        LDSM4(Ah[0], Ah[1], Ah[2], Ah[3], aAh + ks * 32);
        LDSM4(Al[0], Al[1], Al[2], Al[3], aAl + ks * 32);
        uint32_t wrow = ks * 16 * GP * 2;
#pragma unroll
        for (int nt = 0; nt < 8; nt++) {
            uint32_t Bh[4], Bl[4];
            LDSM4T(Bh[0], Bh[1], Bh[2], Bh[3], aWh + wrow + nt * 32);
            LDSM4T(Bl[0], Bl[1], Bl[2], Bl[3], aWl + wrow + nt * 32);
            MMA16816(acc[2 * nt],     Ah, Bh[0], Bh[1]);
            MMA16816(acc[2 * nt],     Al, Bh[0], Bh[1]);
            MMA16816(acc[2 * nt],     Ah, Bl[0], Bl[1]);
            MMA16816(acc[2 * nt + 1], Ah, Bh[2], Bh[3]);
            MMA16816(acc[2 * nt + 1], Al, Bh[2], Bh[3]);
            MMA16816(acc[2 * nt + 1], Ah, Bl[2], Bl[3]);
        }
    }

    const int gid = l >> 2, qid = l & 3;
    const int r0g = m0 + (w << 4) + gid;
    const int r1g = r0g + 8;

    float pa0[4] = {0,0,0,0}, pa1[4] = {0,0,0,0};
    float pb0[4] = {0,0,0,0}, pb1[4] = {0,0,0,0};
#pragma unroll
    for (int t = 0; t < 16; t++) {
        int col = t * 8 + qid * 2;
        float s0 = __ldg(att_src + col), s1 = __ldg(att_src + col + 1);
        float d0 = __ldg(att_dst + col), d1 = __ldg(att_dst + col + 1);
        int h = t >> 2;
        pa0[h] += acc[t][0] * s0 + acc[t][1] * s1;
        pa1[h] += acc[t][2] * s0 + acc[t][3] * s1;
        pb0[h] += acc[t][0] * d0 + acc[t][1] * d1;
        pb1[h] += acc[t][2] * d0 + acc[t][3] * d1;
    }
#pragma unroll
    for (int o = 1; o <= 2; o <<= 1) {
#pragma unroll
        for (int h = 0; h < 4; h++) {
            pa0[h] += __shfl_xor_sync(0xffffffffu, pa0[h], o);
            pa1[h] += __shfl_xor_sync(0xffffffffu, pa1[h], o);
            pb0[h] += __shfl_xor_sync(0xffffffffu, pb0[h], o);
            pb1[h] += __shfl_xor_sync(0xffffffffu, pb1[h], o);
        }
    }

    if (r0g < N_NODES) {
#pragma unroll
        for (int t = 0; t < 16; t++)
            *(__half2*)(g_hh + (size_t)r0g * 128 + t * 8 + qid * 2) =
                __floats2half2_rn(acc[t][0], acc[t][1]);
        if (qid == 0) {
            *(float4*)(g_asrc + (size_t)r0g * 4) = make_float4(pa0[0], pa0[1], pa0[2], pa0[3]);
            *(float4*)(g_adst + (size_t)r0g * 4) = make_float4(pb0[0], pb0[1], pb0[2], pb0[3]);
        }
    }
    if (r1g < N_NODES) {
#pragma unroll
        for (int t = 0; t < 16; t++)
            *(__half2*)(g_hh + (size_t)r1g * 128 + t * 8 + qid * 2) =
                __floats2half2_rn(acc[t][2], acc[t][3]);
        if (qid == 0) {
            *(float4*)(g_asrc + (size_t)r1g * 4) = make_float4(pa1[0], pa1[1], pa1[2], pa1[3]);
            *(float4*)(g_adst + (size_t)r1g * 4) = make_float4(pb1[0], pb1[1], pb1[2], pb1[3]);
        }
    }
}

// ---------------- CSR build ----------------
__global__ void k_count(const int* __restrict__ dst) {
    int t = blockIdx.x * blockDim.x + threadIdx.x;
    if (t >= N_EDGES / 4) return;
    int4 d = ((const int4*)dst)[t];
    atomicAdd(&g_cnt[d.x], 1);
    atomicAdd(&g_cnt[d.y], 1);
    atomicAdd(&g_cnt[d.z], 1);
    atomicAdd(&g_cnt[d.w], 1);
}

__global__ __launch_bounds__(SB) void k_blocksum() {
    __shared__ int wsum[SB / 32];
    int t = blockIdx.x * SB + threadIdx.x;
    int v = (t < N_NODES) ? (g_cnt[t] + 1) : 0;
#pragma unroll
    for (int off = 16; off; off >>= 1) v += __shfl_xor_sync(0xffffffffu, v, off);
    if ((threadIdx.x & 31) == 0) wsum[threadIdx.x >> 5] = v;
    __syncthreads();
    if (threadIdx.x < SB / 32) {
        int s = wsum[threadIdx.x];
#pragma unroll
        for (int off = 16; off; off >>= 1) s += __shfl_xor_sync(0xffffffffu, s, off);
        if (threadIdx.x == 0) g_bsum[blockIdx.x] = s;
    }
}

__global__ void k_topscan() {
    int t = threadIdx.x;
    int v = (t < NB) ? g_bsum[t] : 0;
    int inc = v;
#pragma unroll
    for (int off = 1; off < 32; off <<= 1) {
        int o = __shfl_up_sync(0xffffffffu, inc, off);
        if ((t & 31) >= off) inc += o;
    }
    __shared__ int wtot[2];
    if ((t & 31) == 31) wtot[t >> 5] = inc;
    __syncthreads();
    int base = (t >= 32) ? wtot[0] : 0;
    if (t < NB) g_boff[t] = base + inc - v;   // exclusive
    if (t == 0) g_rowstart[N_NODES] = E_TOT;
}

__global__ __launch_bounds__(SB) void k_writeoff() {
    __shared__ int wsum[SB / 32];
    int t = blockIdx.x * SB + threadIdx.x;
    int lane = threadIdx.x & 31, w = threadIdx.x >> 5;
    int v = (t < N_NODES) ? (g_cnt[t] + 1) : 0;
    int inc = v;
#pragma unroll
    for (int off = 1; off < 32; off <<= 1) {
        int o = __shfl_up_sync(0xffffffffu, inc, off);
        if (lane >= off) inc += o;
    }
    if (lane == 31) wsum[w] = inc;
    __syncthreads();
    if (w == 0) {
        int s = (lane < SB / 32) ? wsum[lane] : 0;
        int si = s;
#pragma unroll
        for (int off = 1; off < 32; off <<= 1) {
            int o = __shfl_up_sync(0xffffffffu, si, off);
            if (lane >= off) si += o;
        }
        if (lane < SB / 32) wsum[lane] = si - s;
    }
    __syncthreads();
    if (t < N_NODES) {
        int pos = g_boff[blockIdx.x] + wsum[w] + inc - v;
        g_rowstart[t] = pos;
        g_cur[t] = pos;
        g_cnt[t] = 0;   // self-reset for next graph replay
    }
}

// ---- placement + fused per-edge attention exp, 4 edges/thread ----
__device__ __forceinline__ float lrelu_exp(float a, float b) {
    float lg = a + b;
    lg = lg > 0.f ? lg : NEG_SLOPE * lg;
    return __expf(lg);     // logits bounded ~|10|: safe shift-free softmax
}

__device__ __forceinline__ void place_one(int s, int d, int e) {
    float4 as = __ldg((const float4*)(g_asrc + (size_t)s * 4));
    float4 ad = __ldg((const float4*)(g_adst + (size_t)d * 4));
    float4 ex;
    ex.x = lrelu_exp(as.x, ad.x);
    ex.y = lrelu_exp(as.y, ad.y);
    ex.z = lrelu_exp(as.z, ad.z);
    ex.w = lrelu_exp(as.w, ad.w);
    int pos = atomicAdd(&g_cur[d], 1);
    g_sed[pos] = make_int2(s, e);
    g_ex[pos]  = ex;
}

// E_TOT/4 threads; 4 independent edges each (int4 loads; MLP=4 per thread)
__global__ void k_place(const int* __restrict__ src, const int* __restrict__ dst) {
    int t = blockIdx.x * blockDim.x + threadIdx.x;
    if (t >= E_TOT / 4) return;
    int e0 = t * 4;
    if (e0 < N_EDGES) {                     // N_EDGES % 4 == 0: clean split
        int4 s4 = ((const int4*)src)[t];
        int4 d4 = ((const int4*)dst)[t];
        place_one(s4.x, d4.x, e0);
        place_one(s4.y, d4.y, e0 + 1);
        place_one(s4.z, d4.z, e0 + 2);
        place_one(s4.w, d4.w, e0 + 3);
    } else {                                // self loops: s == d == e - N_EDGES
#pragma unroll
        for (int i = 0; i < 4; i++) {
            int e = e0 + i;
            int s = e - N_EDGES;
            place_one(s, s, e);
        }
    }
}

// ---------------- K3: aggregate + alpha, one warp per node ----------------
__global__ __launch_bounds__(256) void k_agg(const float* __restrict__ bias,
                                             float* __restrict__ out,
                                             float* __restrict__ alpha_out) {
    int gt = blockIdx.x * blockDim.x + threadIdx.x;
    int warp = gt >> 5, lane = gt & 31;
    int nw = (gridDim.x * blockDim.x) >> 5;
    int hd = lane >> 3;

    const float* exs = (const float*)g_ex;
    float4 b = *(const float4*)(bias + lane * 4);

    for (int n = warp; n < N_NODES; n += nw) {
        int beg = __ldg(&g_rowstart[n]);
        int end = __ldg(&g_rowstart[n + 1]);

        float den = 0.f;
        float4 acc = make_float4(0.f, 0.f, 0.f, 0.f);
#pragma unroll 4
        for (int p = beg; p < end; p++) {
            int s = g_sed[p].x;
            float ex = exs[(size_t)p * 4 + hd];   // one 16B line, warp-broadcast
            den += ex;
            uint2 hv = *(const uint2*)(g_hh + (size_t)s * 128 + lane * 4);
            float2 f0 = __half22float2(*(__half2*)&hv.x);
            float2 f1 = __half22float2(*(__half2*)&hv.y);
            acc.x = fmaf(ex, f0.x, acc.x);
            acc.y = fmaf(ex, f0.y, acc.y);
            acc.z = fmaf(ex, f1.x, acc.z);
            acc.w = fmaf(ex, f1.y, acc.w);
        }

        float inv = 1.f / (den + 1e-16f);
        float4 o;
        o.x = fmaf(acc.x, inv, b.x);
        o.y = fmaf(acc.y, inv, b.y);
        o.z = fmaf(acc.z, inv, b.z);
        o.w = fmaf(acc.w, inv, b.w);
        *(float4*)(out + (size_t)n * 128 + lane * 4) = o;

        if (alpha_out) {
            float i0 = __shfl_sync(0xffffffffu, inv, 0);
            float i1 = __shfl_sync(0xffffffffu, inv, 8);
            float i2 = __shfl_sync(0xffffffffu, inv, 16);
            float i3 = __shfl_sync(0xffffffffu, inv, 24);
            for (int p = beg + lane; p < end; p += 32) {
                float4 v = g_ex[p];
                int e = g_sed[p].y;
                v.x *= i0; v.y *= i1; v.z *= i2; v.w *= i3;
                *(float4*)(alpha_out + (size_t)e * 4) = v;   // write-once
            }
        }
    }
}

// ---------------- launch (R9-proven schedule) ----------------
extern "C" void kernel_launch(void* const* d_in, const int* in_sizes, int n_in,
                              void* d_out, int out_size) {
    const float* x       = (const float*)d_in[0];
    const int*   ei      = (const int*)d_in[1];   // [2, E] int32
    const float* W       = (const float*)d_in[2];
    const float* att_src = (const float*)d_in[3];
    const float* att_dst = (const float*)d_in[4];
    const float* bias    = (const float*)d_in[5];
    float* out = (float*)d_out;

    const int* src = ei;
    const int* dst = ei + N_EDGES;

    float* alpha_out = (out_size >= NHC + E_TOT * HEADS) ? (out + NHC) : nullptr;

    static cudaStream_t s_side = nullptr;
    static cudaEvent_t ev_fork = nullptr, ev_join = nullptr;
    static bool attr_set = false;
    if (!s_side) {
        cudaStreamCreateWithFlags(&s_side, cudaStreamNonBlocking);
        cudaEventCreateWithFlags(&ev_fork, cudaEventDisableTiming);
        cudaEventCreateWithFlags(&ev_join, cudaEventDisableTiming);
    }
    if (!attr_set) {
        cudaFuncSetAttribute(k_gemm, cudaFuncAttributeMaxDynamicSharedMemorySize, GEMM_SMEM);
        attr_set = true;
    }

    // fork: CSR-prefix chain on side stream, GEMM on main stream
    cudaEventRecord(ev_fork, 0);
    cudaStreamWaitEvent(s_side, ev_fork, 0);

    k_count<<<(N_EDGES / 4 + 255) / 256, 256, 0, s_side>>>(dst);
    k_blocksum<<<NB, SB, 0, s_side>>>();
    k_topscan<<<1, 64, 0, s_side>>>();
    k_writeoff<<<NB, SB, 0, s_side>>>();
    cudaEventRecord(ev_join, s_side);

    k_gemm<<<(N_NODES + 127) / 128, 256, GEMM_SMEM>>>(x, W, att_src, att_dst);

    // join: k_place needs g_asrc/g_adst (gemm) and g_cur (writeoff)
    cudaStreamWaitEvent(0, ev_join, 0);

    k_place<<<(E_TOT / 4 + 255) / 256, 256>>>(src, dst);
    k_agg<<<6250, 256>>>(bias, out, alpha_out);
}

// round 14
// speedup vs baseline: 1.0103x; 1.0103x over previous
#include <cuda_runtime.h>
#include <cuda_fp16.h>
#include <math.h>
#include <float.h>
#include <stdint.h>

#define N_NODES 50000
#define N_HALF  25000
#define N_EDGES 1600000
#define E_TOT   1650000      // edges + self loops
#define IN_CH   128
#define HC      128          // HEADS * OUT_CH
#define HEADS   4
#define NHC     (N_NODES * HC)   // 6,400,000
#define NEG_SLOPE 0.2f

#define SB 1024
#define NB ((N_NODES + SB - 1) / SB)   // 49 scan blocks

// GEMM tile config
#define GP 136                       // smem pitch in halves (conflict-free for ldmatrix)
#define GEMM_SMEM (4 * 128 * GP * 2) // sAh, sAl, sWh, sWl

// ---------------- device scratch (static: no allocations allowed) ----------------
__device__ __align__(16) __half g_hh[(size_t)NHC];   // projected features fp16 [N,128]
__device__ __align__(16) float g_asrc[N_NODES * HEADS];
__device__ __align__(16) float g_adst[N_NODES * HEADS];
__device__ int   g_cnt[N_NODES];
__device__ int   g_cur[N_NODES];
__device__ int   g_rowstart[N_NODES + 1];
__device__ int   g_bsum[NB];
__device__ int   g_boff[NB];
__device__ __align__(16) int2   g_sed[E_TOT];        // {src, edge_id} grouped by dst
__device__ __align__(16) float4 g_ex[E_TOT];         // exp(leaky(logit)) per head, CSR order

// ---------------- tensor-core helpers ----------------
#define LDSM4(r0, r1, r2, r3, addr) \
    asm volatile("ldmatrix.sync.aligned.m8n8.x4.shared.b16 {%0,%1,%2,%3}, [%4];" \
                 : "=r"(r0), "=r"(r1), "=r"(r2), "=r"(r3) : "r"(addr))
#define LDSM4T(r0, r1, r2, r3, addr) \
    asm volatile("ldmatrix.sync.aligned.m8n8.x4.trans.shared.b16 {%0,%1,%2,%3}, [%4];" \
                 : "=r"(r0), "=r"(r1), "=r"(r2), "=r"(r3) : "r"(addr))
#define MMA16816(d, a, b0, b1) \
    asm volatile("mma.sync.aligned.m16n8k16.row.col.f32.f16.f16.f32 " \
                 "{%0,%1,%2,%3},{%4,%5,%6,%7},{%8,%9},{%0,%1,%2,%3};" \
                 : "+f"(d[0]), "+f"(d[1]), "+f"(d[2]), "+f"(d[3]) \
                 : "r"(a[0]), "r"(a[1]), "r"(a[2]), "r"(a[3]), "r"(b0), "r"(b1))

__device__ __forceinline__ uint32_t pack_hi(float a, float b) {
    __half2 h = __floats2half2_rn(a, b);
    return *(uint32_t*)&h;
}

// ---------------- K1: h = x @ W via split-fp16 HMMA + fused att dots ----------------
__global__ __launch_bounds__(256, 1) void k_gemm(const float* __restrict__ x,
                                                 const float* __restrict__ W,
                                                 const float* __restrict__ att_src,
                                                 const float* __restrict__ att_dst) {
    extern __shared__ __half sm[];
    __half* sAh = sm;
    __half* sAl = sm + 128 * GP;
    __half* sWh = sm + 2 * 128 * GP;
    __half* sWl = sm + 3 * 128 * GP;

    const int tid = threadIdx.x;
    const int m0  = blockIdx.x * 128;

    const float4* W4 = (const float4*)W;
    for (int i = tid; i < 128 * 32; i += 256) {
        int r = i >> 5, c4 = i & 31;
        float4 wv = W4[i];
        __half h0 = __float2half_rn(wv.x), h1 = __float2half_rn(wv.y);
        __half h2 = __float2half_rn(wv.z), h3 = __float2half_rn(wv.w);
        uint32_t hi01 = pack_hi(wv.x, wv.y), hi23 = pack_hi(wv.z, wv.w);
        uint32_t lo01 = pack_hi(wv.x - __half2float(h0), wv.y - __half2float(h1));
        uint32_t lo23 = pack_hi(wv.z - __half2float(h2), wv.w - __half2float(h3));
        uint32_t off = r * GP + c4 * 4;
        *(uint2*)(sWh + off) = make_uint2(hi01, hi23);
        *(uint2*)(sWl + off) = make_uint2(lo01, lo23);
    }
    const float4* x4 = (const float4*)x;
    for (int i = tid; i < 128 * 32; i += 256) {
        int r = i >> 5, c4 = i & 31;
        int gr = m0 + r;
        float4 v = make_float4(0.f, 0.f, 0.f, 0.f);
        if (gr < N_NODES) v = x4[(size_t)gr * 32 + c4];
        __half h0 = __float2half_rn(v.x), h1 = __float2half_rn(v.y);
        __half h2 = __float2half_rn(v.z), h3 = __float2half_rn(v.w);
        uint32_t hi01 = pack_hi(v.x, v.y), hi23 = pack_hi(v.z, v.w);
        uint32_t lo01 = pack_hi(v.x - __half2float(h0), v.y - __half2float(h1));
        uint32_t lo23 = pack_hi(v.z - __half2float(h2), v.w - __half2float(h3));
        uint32_t off = r * GP + c4 * 4;
        *(uint2*)(sAh + off) = make_uint2(hi01, hi23);
        *(uint2*)(sAl + off) = make_uint2(lo01, lo23);
    }
    __syncthreads();

    const int w = tid >> 5, l = tid & 31;

    float acc[16][4];
#pragma unroll
    for (int t = 0; t < 16; t++)
#pragma unroll
        for (int j = 0; j < 4; j++) acc[t][j] = 0.f;

    int a_m = (w << 4) + (((l >> 3) & 1) << 3) + (l & 7);
    int a_k = ((l >> 4) << 3);
    uint32_t aAh = (uint32_t)__cvta_generic_to_shared(sAh) + (a_m * GP + a_k) * 2;
    uint32_t aAl = (uint32_t)__cvta_generic_to_shared(sAl) + (a_m * GP + a_k) * 2;
    int b_k = (((l >> 3) & 1) << 3) + (l & 7);
    int b_n = ((l >> 4) << 3);
    uint32_t aWh = (uint32_t)__cvta_generic_to_shared(sWh) + (b_k * GP + b_n) * 2;
    uint32_t aWl = (uint32_t)__cvta_generic_to_shared(sWl) + (b_k * GP + b_n) * 2;

#pragma unroll
    for (int ks = 0; ks < 8; ks++) {
        uint32_t Ah[4], Al[4];
        LDSM4(Ah[0], Ah[1], Ah[2], Ah[3], aAh + ks * 32);
        LDSM4(Al[0], Al[1], Al[2], Al[3], aAl + ks * 32);
        uint32_t wrow = ks * 16 * GP * 2;
#pragma unroll
        for (int nt = 0; nt < 8; nt++) {
            uint32_t Bh[4], Bl[4];
            LDSM4T(Bh[0], Bh[1], Bh[2], Bh[3], aWh + wrow + nt * 32);
            LDSM4T(Bl[0], Bl[1], Bl[2], Bl[3], aWl + wrow + nt * 32);
            MMA16816(acc[2 * nt],     Ah, Bh[0], Bh[1]);
            MMA16816(acc[2 * nt],     Al, Bh[0], Bh[1]);
            MMA16816(acc[2 * nt],     Ah, Bl[0], Bl[1]);
            MMA16816(acc[2 * nt + 1], Ah, Bh[2], Bh[3]);
            MMA16816(acc[2 * nt + 1], Al, Bh[2], Bh[3]);
            MMA16816(acc[2 * nt + 1], Ah, Bl[2], Bl[3]);
        }
    }

    const int gid = l >> 2, qid = l & 3;
    const int r0g = m0 + (w << 4) + gid;
    const int r1g = r0g + 8;

    float pa0[4] = {0,0,0,0}, pa1[4] = {0,0,0,0};
    float pb0[4] = {0,0,0,0}, pb1[4] = {0,0,0,0};
#pragma unroll
    for (int t = 0; t < 16; t++) {
        int col = t * 8 + qid * 2;
        float s0 = __ldg(att_src + col), s1 = __ldg(att_src + col + 1);
        float d0 = __ldg(att_dst + col), d1 = __ldg(att_dst + col + 1);
        int h = t >> 2;
        pa0[h] += acc[t][0] * s0 + acc[t][1] * s1;
        pa1[h] += acc[t][2] * s0 + acc[t][3] * s1;
        pb0[h] += acc[t][0] * d0 + acc[t][1] * d1;
        pb1[h] += acc[t][2] * d0 + acc[t][3] * d1;
    }
#pragma unroll
    for (int o = 1; o <= 2; o <<= 1) {
#pragma unroll
        for (int h = 0; h < 4; h++) {
            pa0[h] += __shfl_xor_sync(0xffffffffu, pa0[h], o);
            pa1[h] += __shfl_xor_sync(0xffffffffu, pa1[h], o);
            pb0[h] += __shfl_xor_sync(0xffffffffu, pb0[h], o);
            pb1[h] += __shfl_xor_sync(0xffffffffu, pb1[h], o);
        }
    }

    if (r0g < N_NODES) {
#pragma unroll
        for (int t = 0; t < 16; t++)
            *(__half2*)(g_hh + (size_t)r0g * 128 + t * 8 + qid * 2) =
                __floats2half2_rn(acc[t][0], acc[t][1]);
        if (qid == 0) {
            *(float4*)(g_asrc + (size_t)r0g * 4) = make_float4(pa0[0], pa0[1], pa0[2], pa0[3]);
            *(float4*)(g_adst + (size_t)r0g * 4) = make_float4(pb0[0], pb0[1], pb0[2], pb0[3]);
        }
    }
    if (r1g < N_NODES) {
#pragma unroll
        for (int t = 0; t < 16; t++)
            *(__half2*)(g_hh + (size_t)r1g * 128 + t * 8 + qid * 2) =
                __floats2half2_rn(acc[t][2], acc[t][3]);
        if (qid == 0) {
            *(float4*)(g_asrc + (size_t)r1g * 4) = make_float4(pa1[0], pa1[1], pa1[2], pa1[3]);
            *(float4*)(g_adst + (size_t)r1g * 4) = make_float4(pb1[0], pb1[1], pb1[2], pb1[3]);
        }
    }
}

// ---------------- CSR build (R9-exact) ----------------
__global__ void k_zero_cnt() {
    int t = blockIdx.x * blockDim.x + threadIdx.x;
    if (t < N_NODES) g_cnt[t] = 0;
}

__global__ void k_count(const int* __restrict__ dst) {
    int t = blockIdx.x * blockDim.x + threadIdx.x;
    if (t >= N_EDGES / 4) return;
    int4 d = ((const int4*)dst)[t];
    atomicAdd(&g_cnt[d.x], 1);
    atomicAdd(&g_cnt[d.y], 1);
    atomicAdd(&g_cnt[d.z], 1);
    atomicAdd(&g_cnt[d.w], 1);
}

__global__ __launch_bounds__(SB) void k_blocksum() {
    __shared__ int wsum[SB / 32];
    int t = blockIdx.x * SB + threadIdx.x;
    int v = (t < N_NODES) ? (g_cnt[t] + 1) : 0;
#pragma unroll
    for (int off = 16; off; off >>= 1) v += __shfl_xor_sync(0xffffffffu, v, off);
    if ((threadIdx.x & 31) == 0) wsum[threadIdx.x >> 5] = v;
    __syncthreads();
    if (threadIdx.x < SB / 32) {
        int s = wsum[threadIdx.x];
#pragma unroll
        for (int off = 16; off; off >>= 1) s += __shfl_xor_sync(0xffffffffu, s, off);
        if (threadIdx.x == 0) g_bsum[blockIdx.x] = s;
    }
}

__global__ void k_topscan() {
    int t = threadIdx.x;
    int v = (t < NB) ? g_bsum[t] : 0;
    int inc = v;
#pragma unroll
    for (int off = 1; off < 32; off <<= 1) {
        int o = __shfl_up_sync(0xffffffffu, inc, off);
        if ((t & 31) >= off) inc += o;
    }
    __shared__ int wtot[2];
    if ((t & 31) == 31) wtot[t >> 5] = inc;
    __syncthreads();
    int base = (t >= 32) ? wtot[0] : 0;
    if (t < NB) g_boff[t] = base + inc - v;   // exclusive
    if (t == 0) g_rowstart[N_NODES] = E_TOT;
}

__global__ __launch_bounds__(SB) void k_writeoff() {
    __shared__ int wsum[SB / 32];
    int t = blockIdx.x * SB + threadIdx.x;
    int lane = threadIdx.x & 31, w = threadIdx.x >> 5;
    int v = (t < N_NODES) ? (g_cnt[t] + 1) : 0;
    int inc = v;
#pragma unroll
    for (int off = 1; off < 32; off <<= 1) {
        int o = __shfl_up_sync(0xffffffffu, inc, off);
        if (lane >= off) inc += o;
    }
    if (lane == 31) wsum[w] = inc;
    __syncthreads();
    if (w == 0) {
        int s = (lane < SB / 32) ? wsum[lane] : 0;
        int si = s;
#pragma unroll
        for (int off = 1; off < 32; off <<= 1) {
            int o = __shfl_up_sync(0xffffffffu, si, off);
            if (lane >= off) si += o;
        }
        if (lane < SB / 32) wsum[lane] = si - s;
    }
    __syncthreads();
    if (t < N_NODES) {
        int pos = g_boff[blockIdx.x] + wsum[w] + inc - v;
        g_rowstart[t] = pos;
        g_cur[t] = pos;
    }
}

// ---- placement + fused per-edge attention exp (R9-exact) ----
__device__ __forceinline__ float lrelu_exp(float a, float b) {
    float lg = a + b;
    lg = lg > 0.f ? lg : NEG_SLOPE * lg;
    return __expf(lg);     // logits bounded ~|10|: safe shift-free softmax
}

__global__ void k_place(const int* __restrict__ src, const int* __restrict__ dst) {
    int e = blockIdx.x * blockDim.x + threadIdx.x;
    if (e >= E_TOT) return;
    int d, s;
    if (e < N_EDGES) { s = src[e]; d = dst[e]; }
    else             { s = e - N_EDGES; d = s; }
    float4 as = __ldg((const float4*)(g_asrc + (size_t)s * 4));
    float4 ad = __ldg((const float4*)(g_adst + (size_t)d * 4));
    float4 ex;
    ex.x = lrelu_exp(as.x, ad.x);
    ex.y = lrelu_exp(as.y, ad.y);
    ex.z = lrelu_exp(as.z, ad.z);
    ex.w = lrelu_exp(as.w, ad.w);
    int pos = atomicAdd(&g_cur[d], 1);
    g_sed[pos] = make_int2(s, e);
    g_ex[pos]  = ex;
}

// ---------------- K3: aggregate + alpha, TWO nodes per warp ----------------
__global__ __launch_bounds__(256) void k_agg(const float* __restrict__ bias,
                                             float* __restrict__ out,
                                             float* __restrict__ alpha_out) {
    int gt = blockIdx.x * blockDim.x + threadIdx.x;
    int warp = gt >> 5, lane = gt & 31;
    int hd = lane >> 3;
    if (warp >= N_HALF) return;

    const float* exs = (const float*)g_ex;
    float4 b = *(const float4*)(bias + lane * 4);

    const int nA = warp;
    const int nB = warp + N_HALF;

    int begA = __ldg(&g_rowstart[nA]);
    int endA = __ldg(&g_rowstart[nA + 1]);
    int begB = __ldg(&g_rowstart[nB]);
    int endB = __ldg(&g_rowstart[nB + 1]);
    int lenA = endA - begA, lenB = endB - begB;
    int m = lenA < lenB ? lenA : lenB;

    float denA = 0.f, denB = 0.f;
    float4 accA = make_float4(0.f, 0.f, 0.f, 0.f);
    float4 accB = make_float4(0.f, 0.f, 0.f, 0.f);

    // joint loop: 2 independent gather chains per iteration (8 in flight @ unroll 4)
#pragma unroll 4
    for (int k = 0; k < m; k++) {
        int pA = begA + k, pB = begB + k;
        int sA = g_sed[pA].x;
        int sB = g_sed[pB].x;
        float exA = exs[(size_t)pA * 4 + hd];
        float exB = exs[(size_t)pB * 4 + hd];
        uint2 hvA = *(const uint2*)(g_hh + (size_t)sA * 128 + lane * 4);
        uint2 hvB = *(const uint2*)(g_hh + (size_t)sB * 128 + lane * 4);
        denA += exA; denB += exB;
        float2 a0 = __half22float2(*(__half2*)&hvA.x);
        float2 a1 = __half22float2(*(__half2*)&hvA.y);
        float2 b0 = __half22float2(*(__half2*)&hvB.x);
        float2 b1 = __half22float2(*(__half2*)&hvB.y);
        accA.x = fmaf(exA, a0.x, accA.x); accA.y = fmaf(exA, a0.y, accA.y);
        accA.z = fmaf(exA, a1.x, accA.z); accA.w = fmaf(exA, a1.y, accA.w);
        accB.x = fmaf(exB, b0.x, accB.x); accB.y = fmaf(exB, b0.y, accB.y);
        accB.z = fmaf(exB, b1.x, accB.z); accB.w = fmaf(exB, b1.y, accB.w);
    }
    // tails
#pragma unroll 4
    for (int p = begA + m; p < endA; p++) {
        int s = g_sed[p].x;
        float ex = exs[(size_t)p * 4 + hd];
        uint2 hv = *(const uint2*)(g_hh + (size_t)s * 128 + lane * 4);
        denA += ex;
        float2 f0 = __half22float2(*(__half2*)&hv.x);
        float2 f1 = __half22float2(*(__half2*)&hv.y);
        accA.x = fmaf(ex, f0.x, accA.x); accA.y = fmaf(ex, f0.y, accA.y);
        accA.z = fmaf(ex, f1.x, accA.z); accA.w = fmaf(ex, f1.y, accA.w);
    }
#pragma unroll 4
    for (int p = begB + m; p < endB; p++) {
        int s = g_sed[p].x;
        float ex = exs[(size_t)p * 4 + hd];
        uint2 hv = *(const uint2*)(g_hh + (size_t)s * 128 + lane * 4);
        denB += ex;
        float2 f0 = __half22float2(*(__half2*)&hv.x);
        float2 f1 = __half22float2(*(__half2*)&hv.y);
        accB.x = fmaf(ex, f0.x, accB.x); accB.y = fmaf(ex, f0.y, accB.y);
        accB.z = fmaf(ex, f1.x, accB.z); accB.w = fmaf(ex, f1.y, accB.w);
    }

    float invA = 1.f / (denA + 1e-16f);
    float invB = 1.f / (denB + 1e-16f);
    float4 oA, oB;
    oA.x = fmaf(accA.x, invA, b.x); oA.y = fmaf(accA.y, invA, b.y);
    oA.z = fmaf(accA.z, invA, b.z); oA.w = fmaf(accA.w, invA, b.w);
    oB.x = fmaf(accB.x, invB, b.x); oB.y = fmaf(accB.y, invB, b.y);
    oB.z = fmaf(accB.z, invB, b.z); oB.w = fmaf(accB.w, invB, b.w);
    *(float4*)(out + (size_t)nA * 128 + lane * 4) = oA;
    *(float4*)(out + (size_t)nB * 128 + lane * 4) = oB;

    if (alpha_out) {
        float iA0 = __shfl_sync(0xffffffffu, invA, 0);
        float iA1 = __shfl_sync(0xffffffffu, invA, 8);
        float iA2 = __shfl_sync(0xffffffffu, invA, 16);
        float iA3 = __shfl_sync(0xffffffffu, invA, 24);
        float iB0 = __shfl_sync(0xffffffffu, invB, 0);
        float iB1 = __shfl_sync(0xffffffffu, invB, 8);
        float iB2 = __shfl_sync(0xffffffffu, invB, 16);
        float iB3 = __shfl_sync(0xffffffffu, invB, 24);
        for (int p = begA + lane; p < endA; p += 32) {
            float4 v = g_ex[p];
            int e = g_sed[p].y;
            v.x *= iA0; v.y *= iA1; v.z *= iA2; v.w *= iA3;
            *(float4*)(alpha_out + (size_t)e * 4) = v;
        }
        for (int p = begB + lane; p < endB; p += 32) {
            float4 v = g_ex[p];
            int e = g_sed[p].y;
            v.x *= iB0; v.y *= iB1; v.z *= iB2; v.w *= iB3;
            *(float4*)(alpha_out + (size_t)e * 4) = v;
        }
    }
}

// ---------------- launch (R9-proven schedule) ----------------
extern "C" void kernel_launch(void* const* d_in, const int* in_sizes, int n_in,
                              void* d_out, int out_size) {
    const float* x       = (const float*)d_in[0];
    const int*   ei      = (const int*)d_in[1];   // [2, E] int32
    const float* W       = (const float*)d_in[2];
    const float* att_src = (const float*)d_in[3];
    const float* att_dst = (const float*)d_in[4];
    const float* bias    = (const float*)d_in[5];
    float* out = (float*)d_out;

    const int* src = ei;
    const int* dst = ei + N_EDGES;

    float* alpha_out = (out_size >= NHC + E_TOT * HEADS) ? (out + NHC) : nullptr;

    static cudaStream_t s_side = nullptr;
    static cudaEvent_t ev_fork = nullptr, ev_join = nullptr;
    static bool attr_set = false;
    if (!s_side) {
        cudaStreamCreateWithFlags(&s_side, cudaStreamNonBlocking);
        cudaEventCreateWithFlags(&ev_fork, cudaEventDisableTiming);
        cudaEventCreateWithFlags(&ev_join, cudaEventDisableTiming);
    }
    if (!attr_set) {
        cudaFuncSetAttribute(k_gemm, cudaFuncAttributeMaxDynamicSharedMemorySize, GEMM_SMEM);
        attr_set = true;
    }

    // fork: CSR-prefix chain on side stream, GEMM on main stream
    cudaEventRecord(ev_fork, 0);
    cudaStreamWaitEvent(s_side, ev_fork, 0);

    k_zero_cnt<<<(N_NODES + 255) / 256, 256, 0, s_side>>>();
    k_count<<<(N_EDGES / 4 + 255) / 256, 256, 0, s_side>>>(dst);
    k_blocksum<<<NB, SB, 0, s_side>>>();
    k_topscan<<<1, 64, 0, s_side>>>();
    k_writeoff<<<NB, SB, 0, s_side>>>();
    cudaEventRecord(ev_join, s_side);

    k_gemm<<<(N_NODES + 127) / 128, 256, GEMM_SMEM>>>(x, W, att_src, att_dst);

    // join: k_place needs g_asrc/g_adst (gemm) and g_cur (writeoff)
    cudaStreamWaitEvent(0, ev_join, 0);

    k_place<<<(E_TOT + 255) / 256, 256>>>(src, dst);
    k_agg<<<(N_HALF * 32 + 255) / 256, 256>>>(bias, out, alpha_out);
}

// round 15
// speedup vs baseline: 1.0541x; 1.0433x over previous
#include <cuda_runtime.h>
#include <cuda_fp16.h>
#include <math.h>
#include <float.h>
#include <stdint.h>

#define N_NODES 50000
#define N_EDGES 1600000
#define E_TOT   1650000      // edges + self loops
#define IN_CH   128
#define HC      128          // HEADS * OUT_CH
#define HEADS   4
#define NHC     (N_NODES * HC)   // 6,400,000
#define NEG_SLOPE 0.2f

#define SB 1024
#define NB ((N_NODES + SB - 1) / SB)   // 49 scan blocks

// GEMM tile config
#define GP 136                       // smem pitch in halves (conflict-free for ldmatrix)
#define GEMM_SMEM (4 * 128 * GP * 2) // sAh, sAl, sWh, sWl

// ---------------- device scratch (static: no allocations allowed) ----------------
__device__ __align__(16) __half g_hh[(size_t)NHC];   // projected features fp16 [N,128]
__device__ __align__(16) float g_asrc[N_NODES * HEADS];
__device__ __align__(16) float g_adst[N_NODES * HEADS];
__device__ int   g_cnt[N_NODES];
__device__ int   g_cur[N_NODES];
__device__ int   g_rowstart[N_NODES + 1];
__device__ int   g_bsum[NB];
__device__ int   g_boff[NB];
__device__ __align__(16) int2   g_sed[E_TOT];        // {src, edge_id} grouped by dst
__device__ __align__(16) float4 g_exe[E_TOT];        // exp(leaky(logit)) per head, EDGE order

// ---------------- tensor-core helpers ----------------
#define LDSM4(r0, r1, r2, r3, addr) \
    asm volatile("ldmatrix.sync.aligned.m8n8.x4.shared.b16 {%0,%1,%2,%3}, [%4];" \
                 : "=r"(r0), "=r"(r1), "=r"(r2), "=r"(r3) : "r"(addr))
#define LDSM4T(r0, r1, r2, r3, addr) \
    asm volatile("ldmatrix.sync.aligned.m8n8.x4.trans.shared.b16 {%0,%1,%2,%3}, [%4];" \
                 : "=r"(r0), "=r"(r1), "=r"(r2), "=r"(r3) : "r"(addr))
#define MMA16816(d, a, b0, b1) \
    asm volatile("mma.sync.aligned.m16n8k16.row.col.f32.f16.f16.f32 " \
                 "{%0,%1,%2,%3},{%4,%5,%6,%7},{%8,%9},{%0,%1,%2,%3};" \
                 : "+f"(d[0]), "+f"(d[1]), "+f"(d[2]), "+f"(d[3]) \
                 : "r"(a[0]), "r"(a[1]), "r"(a[2]), "r"(a[3]), "r"(b0), "r"(b1))

__device__ __forceinline__ uint32_t pack_hi(float a, float b) {
    __half2 h = __floats2half2_rn(a, b);
    return *(uint32_t*)&h;
}

// ---------------- K1: h = x @ W via split-fp16 HMMA + fused att dots ----------------
__global__ __launch_bounds__(256, 1) void k_gemm(const float* __restrict__ x,
                                                 const float* __restrict__ W,
                                                 const float* __restrict__ att_src,
                                                 const float* __restrict__ att_dst) {
    extern __shared__ __half sm[];
    __half* sAh = sm;
    __half* sAl = sm + 128 * GP;
    __half* sWh = sm + 2 * 128 * GP;
    __half* sWl = sm + 3 * 128 * GP;

    const int tid = threadIdx.x;
    const int m0  = blockIdx.x * 128;

    const float4* W4 = (const float4*)W;
    for (int i = tid; i < 128 * 32; i += 256) {
        int r = i >> 5, c4 = i & 31;
        float4 wv = W4[i];
        __half h0 = __float2half_rn(wv.x), h1 = __float2half_rn(wv.y);
        __half h2 = __float2half_rn(wv.z), h3 = __float2half_rn(wv.w);
        uint32_t hi01 = pack_hi(wv.x, wv.y), hi23 = pack_hi(wv.z, wv.w);
        uint32_t lo01 = pack_hi(wv.x - __half2float(h0), wv.y - __half2float(h1));
        uint32_t lo23 = pack_hi(wv.z - __half2float(h2), wv.w - __half2float(h3));
        uint32_t off = r * GP + c4 * 4;
        *(uint2*)(sWh + off) = make_uint2(hi01, hi23);
        *(uint2*)(sWl + off) = make_uint2(lo01, lo23);
    }
    const float4* x4 = (const float4*)x;
    for (int i = tid; i < 128 * 32; i += 256) {
        int r = i >> 5, c4 = i & 31;
        int gr = m0 + r;
        float4 v = make_float4(0.f, 0.f, 0.f, 0.f);
        if (gr < N_NODES) v = x4[(size_t)gr * 32 + c4];
        __half h0 = __float2half_rn(v.x), h1 = __float2half_rn(v.y);
        __half h2 = __float2half_rn(v.z), h3 = __float2half_rn(v.w);
        uint32_t hi01 = pack_hi(v.x, v.y), hi23 = pack_hi(v.z, v.w);
        uint32_t lo01 = pack_hi(v.x - __half2float(h0), v.y - __half2float(h1));
        uint32_t lo23 = pack_hi(v.z - __half2float(h2), v.w - __half2float(h3));
        uint32_t off = r * GP + c4 * 4;
        *(uint2*)(sAh + off) = make_uint2(hi01, hi23);
        *(uint2*)(sAl + off) = make_uint2(lo01, lo23);
    }
    __syncthreads();

    const int w = tid >> 5, l = tid & 31;

    float acc[16][4];
#pragma unroll
    for (int t = 0; t < 16; t++)
#pragma unroll
        for (int j = 0; j < 4; j++) acc[t][j] = 0.f;

    int a_m = (w << 4) + (((l >> 3) & 1) << 3) + (l & 7);
    int a_k = ((l >> 4) << 3);
    uint32_t aAh = (uint32_t)__cvta_generic_to_shared(sAh) + (a_m * GP + a_k) * 2;
    uint32_t aAl = (uint32_t)__cvta_generic_to_shared(sAl) + (a_m * GP + a_k) * 2;
    int b_k = (((l >> 3) & 1) << 3) + (l & 7);
    int b_n = ((l >> 4) << 3);
    uint32_t aWh = (uint32_t)__cvta_generic_to_shared(sWh) + (b_k * GP + b_n) * 2;
    uint32_t aWl = (uint32_t)__cvta_generic_to_shared(sWl) + (b_k * GP + b_n) * 2;

#pragma unroll
    for (int ks = 0; ks < 8; ks++) {
        uint32_t Ah[4], Al[4];
        LDSM4(Ah[0], Ah[1], Ah[2], Ah[3], aAh + ks * 32);
        LDSM4(Al[0], Al[1], Al[2], Al[3], aAl + ks * 32);
        uint32_t wrow = ks * 16 * GP * 2;
#pragma unroll
        for (int nt = 0; nt < 8; nt++) {
            uint32_t Bh[4], Bl[4];
            LDSM4T(Bh[0], Bh[1], Bh[2], Bh[3], aWh + wrow + nt * 32);
            LDSM4T(Bl[0], Bl[1], Bl[2], Bl[3], aWl + wrow + nt * 32);
            MMA16816(acc[2 * nt],     Ah, Bh[0], Bh[1]);
            MMA16816(acc[2 * nt],     Al, Bh[0], Bh[1]);
            MMA16816(acc[2 * nt],     Ah, Bl[0], Bl[1]);
            MMA16816(acc[2 * nt + 1], Ah, Bh[2], Bh[3]);
            MMA16816(acc[2 * nt + 1], Al, Bh[2], Bh[3]);
            MMA16816(acc[2 * nt + 1], Ah, Bl[2], Bl[3]);
        }
    }

    const int gid = l >> 2, qid = l & 3;
    const int r0g = m0 + (w << 4) + gid;
    const int r1g = r0g + 8;

    float pa0[4] = {0,0,0,0}, pa1[4] = {0,0,0,0};
    float pb0[4] = {0,0,0,0}, pb1[4] = {0,0,0,0};
#pragma unroll
    for (int t = 0; t < 16; t++) {
        int col = t * 8 + qid * 2;
        float s0 = __ldg(att_src + col), s1 = __ldg(att_src + col + 1);
        float d0 = __ldg(att_dst + col), d1 = __ldg(att_dst + col + 1);
        int h = t >> 2;
        pa0[h] += acc[t][0] * s0 + acc[t][1] * s1;
        pa1[h] += acc[t][2] * s0 + acc[t][3] * s1;
        pb0[h] += acc[t][0] * d0 + acc[t][1] * d1;
        pb1[h] += acc[t][2] * d0 + acc[t][3] * d1;
    }
#pragma unroll
    for (int o = 1; o <= 2; o <<= 1) {
#pragma unroll
        for (int h = 0; h < 4; h++) {
            pa0[h] += __shfl_xor_sync(0xffffffffu, pa0[h], o);
            pa1[h] += __shfl_xor_sync(0xffffffffu, pa1[h], o);
            pb0[h] += __shfl_xor_sync(0xffffffffu, pb0[h], o);
            pb1[h] += __shfl_xor_sync(0xffffffffu, pb1[h], o);
        }
    }

    if (r0g < N_NODES) {
#pragma unroll
        for (int t = 0; t < 16; t++)
            *(__half2*)(g_hh + (size_t)r0g * 128 + t * 8 + qid * 2) =
                __floats2half2_rn(acc[t][0], acc[t][1]);
        if (qid == 0) {
            *(float4*)(g_asrc + (size_t)r0g * 4) = make_float4(pa0[0], pa0[1], pa0[2], pa0[3]);
            *(float4*)(g_adst + (size_t)r0g * 4) = make_float4(pb0[0], pb0[1], pb0[2], pb0[3]);
        }
    }
    if (r1g < N_NODES) {
#pragma unroll
        for (int t = 0; t < 16; t++)
            *(__half2*)(g_hh + (size_t)r1g * 128 + t * 8 + qid * 2) =
                __floats2half2_rn(acc[t][2], acc[t][3]);
        if (qid == 0) {
            *(float4*)(g_asrc + (size_t)r1g * 4) = make_float4(pa1[0], pa1[1], pa1[2], pa1[3]);
            *(float4*)(g_adst + (size_t)r1g * 4) = make_float4(pb1[0], pb1[1], pb1[2], pb1[3]);
        }
    }
}

// ---------------- CSR build ----------------
__global__ void k_zero_cnt() {
    int t = blockIdx.x * blockDim.x + threadIdx.x;
    if (t < N_NODES) g_cnt[t] = 0;
}

__global__ void k_count(const int* __restrict__ dst) {
    int t = blockIdx.x * blockDim.x + threadIdx.x;
    if (t >= N_EDGES / 4) return;
    int4 d = ((const int4*)dst)[t];
    atomicAdd(&g_cnt[d.x], 1);
    atomicAdd(&g_cnt[d.y], 1);
    atomicAdd(&g_cnt[d.z], 1);
    atomicAdd(&g_cnt[d.w], 1);
}

__global__ __launch_bounds__(SB) void k_blocksum() {
    __shared__ int wsum[SB / 32];
    int t = blockIdx.x * SB + threadIdx.x;
    int v = (t < N_NODES) ? (g_cnt[t] + 1) : 0;
#pragma unroll
    for (int off = 16; off; off >>= 1) v += __shfl_xor_sync(0xffffffffu, v, off);
    if ((threadIdx.x & 31) == 0) wsum[threadIdx.x >> 5] = v;
    __syncthreads();
    if (threadIdx.x < SB / 32) {
        int s = wsum[threadIdx.x];
#pragma unroll
        for (int off = 16; off; off >>= 1) s += __shfl_xor_sync(0xffffffffu, s, off);
        if (threadIdx.x == 0) g_bsum[blockIdx.x] = s;
    }
}

__global__ void k_topscan() {
    int t = threadIdx.x;
    int v = (t < NB) ? g_bsum[t] : 0;
    int inc = v;
#pragma unroll
    for (int off = 1; off < 32; off <<= 1) {
        int o = __shfl_up_sync(0xffffffffu, inc, off);
        if ((t & 31) >= off) inc += o;
    }
    __shared__ int wtot[2];
    if ((t & 31) == 31) wtot[t >> 5] = inc;
    __syncthreads();
    int base = (t >= 32) ? wtot[0] : 0;
    if (t < NB) g_boff[t] = base + inc - v;   // exclusive
    if (t == 0) g_rowstart[N_NODES] = E_TOT;
}

__global__ __launch_bounds__(SB) void k_writeoff() {
    __shared__ int wsum[SB / 32];
    int t = blockIdx.x * SB + threadIdx.x;
    int lane = threadIdx.x & 31, w = threadIdx.x >> 5;
    int v = (t < N_NODES) ? (g_cnt[t] + 1) : 0;
    int inc = v;
#pragma unroll
    for (int off = 1; off < 32; off <<= 1) {
        int o = __shfl_up_sync(0xffffffffu, inc, off);
        if (lane >= off) inc += o;
    }
    if (lane == 31) wsum[w] = inc;
    __syncthreads();
    if (w == 0) {
        int s = (lane < SB / 32) ? wsum[lane] : 0;
        int si = s;
#pragma unroll
        for (int off = 1; off < 32; off <<= 1) {
            int o = __shfl_up_sync(0xffffffffu, si, off);
            if (lane >= off) si += o;
        }
        if (lane < SB / 32) wsum[lane] = si - s;
    }
    __syncthreads();
    if (t < N_NODES) {
        int pos = g_boff[blockIdx.x] + wsum[w] + inc - v;
        g_rowstart[t] = pos;
        g_cur[t] = pos;
    }
}

// ---- CSR scatter only (no GEMM dependency): runs concurrent with GEMM ----
__global__ void k_scatter(const int* __restrict__ src, const int* __restrict__ dst) {
    int e = blockIdx.x * blockDim.x + threadIdx.x;
    if (e >= E_TOT) return;
    int d, s;
    if (e < N_EDGES) { s = src[e]; d = dst[e]; }
    else             { s = e - N_EDGES; d = s; }
    int pos = atomicAdd(&g_cur[d], 1);
    g_sed[pos] = make_int2(s, e);
}

// ---- per-edge attention exp in EDGE order (no CSR dependency): after GEMM ----
__device__ __forceinline__ float lrelu_exp(float a, float b) {
    float lg = a + b;
    lg = lg > 0.f ? lg : NEG_SLOPE * lg;
    return __expf(lg);     // logits bounded ~|10|: safe shift-free softmax
}

__global__ void k_ex(const int* __restrict__ src, const int* __restrict__ dst) {
    int e = blockIdx.x * blockDim.x + threadIdx.x;
    if (e >= E_TOT) return;
    int d, s;
    if (e < N_EDGES) { s = src[e]; d = dst[e]; }
    else             { s = e - N_EDGES; d = s; }
    float4 as = __ldg((const float4*)(g_asrc + (size_t)s * 4));
    float4 ad = __ldg((const float4*)(g_adst + (size_t)d * 4));
    float4 ex;
    ex.x = lrelu_exp(as.x, ad.x);
    ex.y = lrelu_exp(as.y, ad.y);
    ex.z = lrelu_exp(as.z, ad.z);
    ex.w = lrelu_exp(as.w, ad.w);
    g_exe[e] = ex;                       // coalesced write
}

// ---------------- K3: aggregate + alpha, one warp per node ----------------
__global__ __launch_bounds__(256) void k_agg(const float* __restrict__ bias,
                                             float* __restrict__ out,
                                             float* __restrict__ alpha_out) {
    int gt = blockIdx.x * blockDim.x + threadIdx.x;
    int warp = gt >> 5, lane = gt & 31;
    int nw = (gridDim.x * blockDim.x) >> 5;
    int hd = lane >> 3;

    const float* exs = (const float*)g_exe;
    float4 b = *(const float4*)(bias + lane * 4);

    for (int n = warp; n < N_NODES; n += nw) {
        int beg = __ldg(&g_rowstart[n]);
        int end = __ldg(&g_rowstart[n + 1]);

        float den = 0.f;
        float4 acc = make_float4(0.f, 0.f, 0.f, 0.f);
#pragma unroll 4
        for (int p = beg; p < end; p++) {
            int2 se = g_sed[p];
            float ex = exs[(size_t)se.y * 4 + hd];   // gather, parallel to h gather
            uint2 hv = *(const uint2*)(g_hh + (size_t)se.x * 128 + lane * 4);
            den += ex;
            float2 f0 = __half22float2(*(__half2*)&hv.x);
            float2 f1 = __half22float2(*(__half2*)&hv.y);
            acc.x = fmaf(ex, f0.x, acc.x);
            acc.y = fmaf(ex, f0.y, acc.y);
            acc.z = fmaf(ex, f1.x, acc.z);
            acc.w = fmaf(ex, f1.y, acc.w);
        }

        float inv = 1.f / (den + 1e-16f);
        float4 o;
        o.x = fmaf(acc.x, inv, b.x);
        o.y = fmaf(acc.y, inv, b.y);
        o.z = fmaf(acc.z, inv, b.z);
        o.w = fmaf(acc.w, inv, b.w);
        *(float4*)(out + (size_t)n * 128 + lane * 4) = o;

        if (alpha_out) {
            float i0 = __shfl_sync(0xffffffffu, inv, 0);
            float i1 = __shfl_sync(0xffffffffu, inv, 8);
            float i2 = __shfl_sync(0xffffffffu, inv, 16);
            float i3 = __shfl_sync(0xffffffffu, inv, 24);
            for (int p = beg + lane; p < end; p += 32) {
                int e = g_sed[p].y;
                float4 v = g_exe[e];
                v.x *= i0; v.y *= i1; v.z *= i2; v.w *= i3;
                *(float4*)(alpha_out + (size_t)e * 4) = v;   // write-once
            }
        }
    }
}

// ---------------- launch ----------------
extern "C" void kernel_launch(void* const* d_in, const int* in_sizes, int n_in,
                              void* d_out, int out_size) {
    const float* x       = (const float*)d_in[0];
    const int*   ei      = (const int*)d_in[1];   // [2, E] int32
    const float* W       = (const float*)d_in[2];
    const float* att_src = (const float*)d_in[3];
    const float* att_dst = (const float*)d_in[4];
    const float* bias    = (const float*)d_in[5];
    float* out = (float*)d_out;

    const int* src = ei;
    const int* dst = ei + N_EDGES;

    float* alpha_out = (out_size >= NHC + E_TOT * HEADS) ? (out + NHC) : nullptr;

    static cudaStream_t s_side = nullptr;
    static cudaEvent_t ev_fork = nullptr, ev_join = nullptr;
    static bool attr_set = false;
    if (!s_side) {
        cudaStreamCreateWithFlags(&s_side, cudaStreamNonBlocking);
        cudaEventCreateWithFlags(&ev_fork, cudaEventDisableTiming);
        cudaEventCreateWithFlags(&ev_join, cudaEventDisableTiming);
    }
    if (!attr_set) {
        cudaFuncSetAttribute(k_gemm, cudaFuncAttributeMaxDynamicSharedMemorySize, GEMM_SMEM);
        attr_set = true;
    }

    // fork: full CSR chain INCLUDING scatter on side stream (no GEMM dependency)
    cudaEventRecord(ev_fork, 0);
    cudaStreamWaitEvent(s_side, ev_fork, 0);

    k_zero_cnt<<<(N_NODES + 255) / 256, 256, 0, s_side>>>();
    k_count<<<(N_EDGES / 4 + 255) / 256, 256, 0, s_side>>>(dst);
    k_blocksum<<<NB, SB, 0, s_side>>>();
    k_topscan<<<1, 64, 0, s_side>>>();
    k_writeoff<<<NB, SB, 0, s_side>>>();
    k_scatter<<<(E_TOT + 255) / 256, 256, 0, s_side>>>(src, dst);
    cudaEventRecord(ev_join, s_side);

    // main: GEMM then edge-order exp (needs only GEMM output; coalesced)
    k_gemm<<<(N_NODES + 127) / 128, 256, GEMM_SMEM>>>(x, W, att_src, att_dst);
    k_ex<<<(E_TOT + 255) / 256, 256>>>(src, dst);

    // join: agg needs g_sed (side) + g_exe/g_hh (main)
    cudaStreamWaitEvent(0, ev_join, 0);
    k_agg<<<6250, 256>>>(bias, out, alpha_out);
}